// round 2
// baseline (speedup 1.0000x reference)
#include <cuda_runtime.h>

#define NN 50000
#define NE 800000
#define ET (NN + NE)      // edges + self loops
#define NG 64

// ---------------- scratch (static device globals; no runtime alloc) --------
__device__ float g_h  [NN * 64];    // after init MLP
__device__ float g_xl1[NN * 256];
__device__ float g_xr1[NN * 256];
__device__ float g_h1 [NN * 256];   // GAT1 output (post-ELU)
__device__ float g_xl2[NN * 64];
__device__ float g_xr2[NN * 64];
__device__ float g_h2 [NN * 64];    // GAT2 output (post-ELU)
__device__ int   g_deg[NN];
__device__ int   g_rowptr[NN + 1];
__device__ int   g_cursor[NN];
__device__ int   g_csr[ET];         // src per incoming edge, grouped by dst
__device__ float g_sums[NG * 64];
__device__ int   g_cnts[NG];
__device__ int   g_is64;            // 1 if index tensors are int64, 0 if int32

// ---------------- index helpers --------------------------------------------
__device__ __forceinline__ int ld_idx(const int* __restrict__ p, int i, int is64, int lim) {
    int v = is64 ? p[2 * i] : p[i];
    // clamp: crash-proof against any misinterpretation
    v = v < 0 ? 0 : v;
    v = v >= lim ? lim - 1 : v;
    return v;
}

// detect int64 vs int32 for edge_index: int64 node ids < 50000 have zero hi words
__global__ void k_detect(const int* __restrict__ ei32) {
    if (threadIdx.x == 0) {
        int nz = 0;
        #pragma unroll 1
        for (int i = 0; i < 512; i++) nz |= ei32[2 * i + 1];
        #pragma unroll 1
        for (int i = 0; i < 512; i++) nz |= ei32[NE + 2 * i + 1];   // sample deeper
        g_is64 = (nz == 0) ? 1 : 0;
    }
}

// ---------------- CSR build ------------------------------------------------
__global__ void k_init() {
    int t = blockIdx.x * blockDim.x + threadIdx.x;
    if (t < NN) g_deg[t] = 1;                 // self loop
    if (t < NG * 64) g_sums[t] = 0.f;
    if (t < NG) g_cnts[t] = 0;
}

__global__ void k_deg(const int* __restrict__ ei) {
    int e = blockIdx.x * blockDim.x + threadIdx.x;
    if (e < NE) {
        int is64 = g_is64;
        int d = ld_idx(ei, NE + e, is64, NN);
        atomicAdd(&g_deg[d], 1);
    }
}

__global__ void k_scan() {
    __shared__ int ssum[1024];
    int t = threadIdx.x;
    const int chunk = (NN + 1023) / 1024;     // 49
    int beg = t * chunk;
    int end = beg + chunk; if (end > NN) end = NN;
    int s = 0;
    for (int i = beg; i < end; i++) s += g_deg[i];
    ssum[t] = s;
    __syncthreads();
    for (int off = 1; off < 1024; off <<= 1) {
        int v = (t >= off) ? ssum[t - off] : 0;
        __syncthreads();
        ssum[t] += v;
        __syncthreads();
    }
    int run = (t == 0) ? 0 : ssum[t - 1];
    for (int i = beg; i < end; i++) {
        g_rowptr[i] = run;
        g_cursor[i] = run;
        run += g_deg[i];
    }
    if (t == 1023) g_rowptr[NN] = run;
}

__global__ void k_scatter(const int* __restrict__ ei) {
    int e = blockIdx.x * blockDim.x + threadIdx.x;
    int is64 = g_is64;
    if (e < NE) {
        int s = ld_idx(ei, e, is64, NN);
        int d = ld_idx(ei, NE + e, is64, NN);
        int p = atomicAdd(&g_cursor[d], 1);
        if (p < ET) g_csr[p] = s;
    } else if (e < ET) {
        int i = e - NE;
        int p = atomicAdd(&g_cursor[i], 1);
        if (p < ET) g_csr[p] = i;              // self loop
    }
}

// ---------------- node feature MLP -----------------------------------------
// block = 256 threads = 4 nodes x 64 lanes
__global__ void k_node(const float* __restrict__ x,
                       const float* __restrict__ catW, const float* __restrict__ catb,
                       const float* __restrict__ initW, const float* __restrict__ initb) {
    __shared__ float s_x[4][40];
    __shared__ float s_s[4][32];
    int sub = threadIdx.x & 63;
    int ln  = threadIdx.x >> 6;
    int n = blockIdx.x * 4 + ln;
    if (sub < 40) s_x[ln][sub] = x[n * 40 + sub];
    __syncthreads();
    if (sub < 32) {
        float a = catb[sub];
        #pragma unroll
        for (int k = 0; k < 24; k++) a += s_x[ln][k] * catW[k * 32 + sub];
        s_s[ln][sub] = fmaxf(a, 0.f);
    }
    __syncthreads();
    float a = initb[sub];
    #pragma unroll
    for (int k = 0; k < 16; k++) a += s_x[ln][24 + k] * initW[k * 64 + sub];
    #pragma unroll
    for (int k = 0; k < 32; k++) a += s_s[ln][k] * initW[(16 + k) * 64 + sub];
    g_h[n * 64 + sub] = fmaxf(a, 0.f);
}

// ---------------- linear 1: h[N,64] @ Wl/Wr[64,256] -> xl1,xr1 -------------
__global__ void k_lin1(const float* __restrict__ Wl, const float* __restrict__ bl,
                       const float* __restrict__ Wr, const float* __restrict__ br) {
    __shared__ float xs[8][64];
    int j = threadIdx.x;
    int base = blockIdx.x * 8;
    for (int t = j; t < 8 * 64; t += 256)
        xs[t >> 6][t & 63] = g_h[(base + (t >> 6)) * 64 + (t & 63)];
    __syncthreads();
    float al[8], ar[8];
    float bbl = bl[j], bbr = br[j];
    #pragma unroll
    for (int n = 0; n < 8; n++) { al[n] = bbl; ar[n] = bbr; }
    for (int k = 0; k < 64; k++) {
        float wl = Wl[k * 256 + j];
        float wr = Wr[k * 256 + j];
        #pragma unroll
        for (int n = 0; n < 8; n++) {
            float xv = xs[n][k];
            al[n] = fmaf(xv, wl, al[n]);
            ar[n] = fmaf(xv, wr, ar[n]);
        }
    }
    #pragma unroll
    for (int n = 0; n < 8; n++) {
        g_xl1[(base + n) * 256 + j] = al[n];
        g_xr1[(base + n) * 256 + j] = ar[n];
    }
}

// ---------------- GAT layer 1 (4 heads x 64): warp per dst node ------------
__global__ void k_gat1(const float* __restrict__ att, const float* __restrict__ bias) {
    int w = (blockIdx.x * blockDim.x + threadIdx.x) >> 5;
    int lane = threadIdx.x & 31;
    if (w >= NN) return;
    float xr[8], atv[8], acc[8];
    float m[4], den[4];
    const float* xrp = g_xr1 + (long)w * 256;
    #pragma unroll
    for (int i = 0; i < 8; i++) {
        int idx = lane + 32 * i;
        xr[i]  = xrp[idx];
        atv[i] = att[idx];
        acc[i] = 0.f;
    }
    #pragma unroll
    for (int h = 0; h < 4; h++) { m[h] = -1e30f; den[h] = 0.f; }

    int p0 = g_rowptr[w], p1 = g_rowptr[w + 1];
    for (int p = p0; p < p1; p++) {
        int s = g_csr[p];
        s = s < 0 ? 0 : (s >= NN ? NN - 1 : s);
        const float* xlp = g_xl1 + (long)s * 256;
        float xl[8];
        #pragma unroll
        for (int i = 0; i < 8; i++) xl[i] = xlp[lane + 32 * i];
        float part[4] = {0.f, 0.f, 0.f, 0.f};
        #pragma unroll
        for (int i = 0; i < 8; i++) {
            float v = xl[i] + xr[i];
            float t = fmaxf(v, 0.2f * v);        // leaky relu
            part[i >> 1] = fmaf(t, atv[i], part[i >> 1]);
        }
        #pragma unroll
        for (int off = 16; off > 0; off >>= 1) {
            #pragma unroll
            for (int h = 0; h < 4; h++)
                part[h] += __shfl_xor_sync(0xffffffffu, part[h], off);
        }
        #pragma unroll
        for (int h = 0; h < 4; h++) {
            float e  = part[h];
            float mn = fmaxf(m[h], e);
            float sc = __expf(m[h] - mn);
            float wv = __expf(e - mn);
            den[h] = den[h] * sc + wv;
            m[h] = mn;
            acc[2 * h]     = acc[2 * h]     * sc + wv * xl[2 * h];
            acc[2 * h + 1] = acc[2 * h + 1] * sc + wv * xl[2 * h + 1];
        }
    }
    float* out = g_h1 + (long)w * 256;
    #pragma unroll
    for (int i = 0; i < 8; i++) {
        int idx = lane + 32 * i;
        float v = acc[i] / den[i >> 1] + bias[idx];
        out[idx] = v > 0.f ? v : (__expf(v) - 1.f);   // ELU
    }
}

// ---------------- linear 2: h1[N,256] @ Wl/Wr[256,64] -> xl2,xr2 -----------
__global__ void k_lin2(const float* __restrict__ Wl, const float* __restrict__ bl,
                       const float* __restrict__ Wr, const float* __restrict__ br) {
    __shared__ float xs[16][256];
    int tid = threadIdx.x;
    int j = tid & 63;
    int q = tid >> 6;
    int base = blockIdx.x * 16;
    for (int t = tid; t < 16 * 256; t += 256)
        xs[t >> 8][t & 255] = g_h1[(long)(base + (t >> 8)) * 256 + (t & 255)];
    __syncthreads();
    float al[4], ar[4];
    float bbl = bl[j], bbr = br[j];
    #pragma unroll
    for (int n = 0; n < 4; n++) { al[n] = bbl; ar[n] = bbr; }
    for (int k = 0; k < 256; k++) {
        float wl = Wl[k * 64 + j];
        float wr = Wr[k * 64 + j];
        #pragma unroll
        for (int n = 0; n < 4; n++) {
            float xv = xs[q + 4 * n][k];
            al[n] = fmaf(xv, wl, al[n]);
            ar[n] = fmaf(xv, wr, ar[n]);
        }
    }
    #pragma unroll
    for (int n = 0; n < 4; n++) {
        int node = base + q + 4 * n;
        g_xl2[node * 64 + j] = al[n];
        g_xr2[node * 64 + j] = ar[n];
    }
}

// ---------------- GAT layer 2 (1 head x 64): warp per dst node -------------
__global__ void k_gat2(const float* __restrict__ att, const float* __restrict__ bias) {
    int w = (blockIdx.x * blockDim.x + threadIdx.x) >> 5;
    int lane = threadIdx.x & 31;
    if (w >= NN) return;
    const float* xrp = g_xr2 + (long)w * 64;
    float xr0 = xrp[lane], xr1 = xrp[lane + 32];
    float at0 = att[lane], at1 = att[lane + 32];
    float acc0 = 0.f, acc1 = 0.f, m = -1e30f, den = 0.f;

    int p0 = g_rowptr[w], p1 = g_rowptr[w + 1];
    for (int p = p0; p < p1; p++) {
        int s = g_csr[p];
        s = s < 0 ? 0 : (s >= NN ? NN - 1 : s);
        const float* xlp = g_xl2 + (long)s * 64;
        float xl0 = xlp[lane], xl1 = xlp[lane + 32];
        float v0 = xl0 + xr0, v1 = xl1 + xr1;
        float t0 = fmaxf(v0, 0.2f * v0);
        float t1 = fmaxf(v1, 0.2f * v1);
        float part = fmaf(t0, at0, t1 * at1);
        #pragma unroll
        for (int off = 16; off > 0; off >>= 1)
            part += __shfl_xor_sync(0xffffffffu, part, off);
        float mn = fmaxf(m, part);
        float sc = __expf(m - mn);
        float wv = __expf(part - mn);
        den = den * sc + wv;
        m = mn;
        acc0 = acc0 * sc + wv * xl0;
        acc1 = acc1 * sc + wv * xl1;
    }
    float* out = g_h2 + (long)w * 64;
    float v0 = acc0 / den + bias[lane];
    float v1 = acc1 / den + bias[lane + 32];
    out[lane]      = v0 > 0.f ? v0 : (__expf(v0) - 1.f);
    out[lane + 32] = v1 > 0.f ? v1 : (__expf(v1) - 1.f);
}

// ---------------- mean pool ------------------------------------------------
__global__ void k_pool(const int* __restrict__ batch) {
    int t = blockIdx.x * blockDim.x + threadIdx.x;
    if (t >= NN * 64) return;
    int n = t >> 6, j = t & 63;
    int is64 = g_is64;
    int g = ld_idx(batch, n, is64, NG);
    atomicAdd(&g_sums[g * 64 + j], g_h2[t]);
    if (j == 0) atomicAdd(&g_cnts[g], 1);
}

// ---------------- output head ----------------------------------------------
__global__ void k_out(const float* __restrict__ W, const float* __restrict__ b,
                      float* __restrict__ out) {
    int t = blockIdx.x * blockDim.x + threadIdx.x;
    if (t >= NG * 64) return;
    int g = t >> 6, j = t & 63;
    float c = fmaxf((float)g_cnts[g], 1.f);
    float inv = 1.f / c;
    float a = b[j];
    #pragma unroll
    for (int k = 0; k < 64; k++)
        a = fmaf(g_sums[g * 64 + k] * inv, W[k * 64 + j], a);
    out[t] = a;
}

// ---------------- launch ----------------------------------------------------
extern "C" void kernel_launch(void* const* d_in, const int* in_sizes, int n_in,
                              void* d_out, int out_size) {
    // Expected element counts in setup_inputs() dict order.
    static const int EXP[21] = {
        2000000, 1600000, 50000,        // x, edge_index, batch
        768, 32, 3072, 64,              // cat_W, cat_b, init_W, init_b
        16384, 256, 16384, 256,         // c1_Wl, c1_bl, c1_Wr, c1_br
        256, 256,                       // c1_att, c1_bias
        16384, 64, 16384, 64,           // c2_Wl, c2_bl, c2_Wr, c2_br
        64, 64,                         // c2_att, c2_bias
        4096, 64                        // out_W, out_b
    };
    const void* in[21];
    bool direct = (n_in >= 21);
    if (direct)
        for (int i = 0; i < 21; i++)
            if (in_sizes[i] != EXP[i]) { direct = false; break; }
    if (direct) {
        for (int i = 0; i < 21; i++) in[i] = d_in[i];
    } else {
        // greedy match by element count (handles any reordering with same sizes)
        bool used[64] = {false};
        for (int j = 0; j < 21; j++) {
            in[j] = d_in[j < n_in ? j : 0];  // fallback
            for (int i = 0; i < n_in && i < 64; i++) {
                if (!used[i] && in_sizes[i] == EXP[j]) {
                    in[j] = d_in[i]; used[i] = true; break;
                }
            }
        }
    }

    const float* x      = (const float*)in[0];
    const int*   ei     = (const int*)in[1];     // int32 view; k_detect picks width
    const int*   batch  = (const int*)in[2];
    const float* cat_W  = (const float*)in[3];
    const float* cat_b  = (const float*)in[4];
    const float* init_W = (const float*)in[5];
    const float* init_b = (const float*)in[6];
    const float* c1_Wl  = (const float*)in[7];
    const float* c1_bl  = (const float*)in[8];
    const float* c1_Wr  = (const float*)in[9];
    const float* c1_br  = (const float*)in[10];
    const float* c1_att = (const float*)in[11];
    const float* c1_bias= (const float*)in[12];
    const float* c2_Wl  = (const float*)in[13];
    const float* c2_bl  = (const float*)in[14];
    const float* c2_Wr  = (const float*)in[15];
    const float* c2_br  = (const float*)in[16];
    const float* c2_att = (const float*)in[17];
    const float* c2_bias= (const float*)in[18];
    const float* out_W  = (const float*)in[19];
    const float* out_b  = (const float*)in[20];
    float* out = (float*)d_out;

    k_detect<<<1, 32>>>(ei);
    k_init<<<(NN + 255) / 256, 256>>>();
    k_deg<<<(NE + 255) / 256, 256>>>(ei);
    k_scan<<<1, 1024>>>();
    k_scatter<<<(ET + 255) / 256, 256>>>(ei);

    k_node<<<NN / 4, 256>>>(x, cat_W, cat_b, init_W, init_b);
    k_lin1<<<NN / 8, 256>>>(c1_Wl, c1_bl, c1_Wr, c1_br);
    k_gat1<<<NN / 8, 256>>>(c1_att, c1_bias);
    k_lin2<<<NN / 16, 256>>>(c2_Wl, c2_bl, c2_Wr, c2_br);
    k_gat2<<<NN / 8, 256>>>(c2_att, c2_bias);
    k_pool<<<(NN * 64 + 255) / 256, 256>>>(batch);
    k_out<<<16, 256>>>(out_W, out_b, out);
}

// round 5
// speedup vs baseline: 1.3293x; 1.3293x over previous
#include <cuda_runtime.h>

#define NN 50000
#define NE 800000
#define ET (NN + NE)      // edges + self loops
#define NG 64
#define NB 196            // scan blocks: ceil(NN/256)

// ---------------- scratch (static device globals; no runtime alloc) --------
__device__ float  g_h   [NN * 64];   // after init MLP
__device__ float  g_xl1 [NN * 256];
__device__ float  g_xr1 [NN * 256];
__device__ float  g_h1  [NN * 256];  // GAT1 output (post-ELU)
__device__ float  g_xl2 [NN * 64];
__device__ float  g_xr2 [NN * 64];
__device__ float  g_h2  [NN * 64];   // GAT2 output (post-ELU)
__device__ int    g_deg[NN];
__device__ int    g_rowptr[NN + 1];
__device__ int    g_cursor[NN];
__device__ int    g_csr[ET];         // src per incoming edge, grouped by dst
__device__ int    g_bsum[256];
__device__ int    g_boff[256];
__device__ float  g_sums[NG * 64];
__device__ int    g_cnts[NG];
__device__ int    g_is64;            // 1 if index tensors are int64, 0 if int32

// ---------------- index helpers --------------------------------------------
__device__ __forceinline__ int ld_idx(const int* __restrict__ p, int i, int is64, int lim) {
    int v = is64 ? p[2 * i] : p[i];
    v = v < 0 ? 0 : v;
    v = v >= lim ? lim - 1 : v;
    return v;
}

// ---------------- init + dtype detect --------------------------------------
__global__ void k_init(const int* __restrict__ ei32) {
    int t = blockIdx.x * blockDim.x + threadIdx.x;
    if (t < NN) g_deg[t] = 1;                 // self loop
    if (t < NG * 64) g_sums[t] = 0.f;
    if (t < NG) g_cnts[t] = 0;
    if (blockIdx.x == 0 && threadIdx.x < 32) {
        int lane = threadIdx.x;
        int nz = 0;
        #pragma unroll
        for (int i = 0; i < 8; i++) {
            nz |= ei32[2 * (lane * 8 + i) + 1];
            nz |= ei32[NE + 2 * (lane * 8 + i) + 1];
        }
        #pragma unroll
        for (int off = 16; off > 0; off >>= 1)
            nz |= __shfl_xor_sync(0xffffffffu, nz, off);
        if (lane == 0) g_is64 = (nz == 0) ? 1 : 0;
    }
}

__global__ void k_deg(const int* __restrict__ ei) {
    int e = blockIdx.x * blockDim.x + threadIdx.x;
    if (e < NE) {
        int d = ld_idx(ei, NE + e, g_is64, NN);
        atomicAdd(&g_deg[d], 1);
    }
}

// ---------------- parallel 3-phase scan ------------------------------------
__global__ void k_scan1() {
    __shared__ int sh[256];
    int t = threadIdx.x;
    int i = blockIdx.x * 256 + t;
    sh[t] = (i < NN) ? g_deg[i] : 0;
    __syncthreads();
    #pragma unroll
    for (int off = 128; off > 0; off >>= 1) {
        if (t < off) sh[t] += sh[t + off];
        __syncthreads();
    }
    if (t == 0) g_bsum[blockIdx.x] = sh[0];
}

__global__ void k_scan2() {
    __shared__ int sh[256];
    int t = threadIdx.x;
    int own = (t < NB) ? g_bsum[t] : 0;
    sh[t] = own;
    __syncthreads();
    #pragma unroll
    for (int off = 1; off < 256; off <<= 1) {
        int v = (t >= off) ? sh[t - off] : 0;
        __syncthreads();
        sh[t] += v;
        __syncthreads();
    }
    if (t < NB) g_boff[t] = sh[t] - own;      // exclusive
    if (t == 255) g_rowptr[NN] = sh[255];
}

__global__ void k_scan3() {
    __shared__ int sh[256];
    int t = threadIdx.x;
    int i = blockIdx.x * 256 + t;
    int d = (i < NN) ? g_deg[i] : 0;
    sh[t] = d;
    __syncthreads();
    #pragma unroll
    for (int off = 1; off < 256; off <<= 1) {
        int v = (t >= off) ? sh[t - off] : 0;
        __syncthreads();
        sh[t] += v;
        __syncthreads();
    }
    if (i < NN) {
        int excl = sh[t] - d + g_boff[blockIdx.x];
        g_rowptr[i] = excl;
        g_cursor[i] = excl;
    }
}

__global__ void k_scatter(const int* __restrict__ ei) {
    int e = blockIdx.x * blockDim.x + threadIdx.x;
    int is64 = g_is64;
    if (e < NE) {
        int s = ld_idx(ei, e, is64, NN);
        int d = ld_idx(ei, NE + e, is64, NN);
        int p = atomicAdd(&g_cursor[d], 1);
        if (p < ET) g_csr[p] = s;
    } else if (e < ET) {
        int i = e - NE;
        int p = atomicAdd(&g_cursor[i], 1);
        if (p < ET) g_csr[p] = i;              // self loop
    }
}

// ---------------- node feature MLP -----------------------------------------
__global__ void k_node(const float* __restrict__ x,
                       const float* __restrict__ catW, const float* __restrict__ catb,
                       const float* __restrict__ initW, const float* __restrict__ initb) {
    __shared__ float s_x[4][40];
    __shared__ float s_s[4][32];
    int sub = threadIdx.x & 63;
    int ln  = threadIdx.x >> 6;
    int n = blockIdx.x * 4 + ln;
    if (sub < 40) s_x[ln][sub] = x[n * 40 + sub];
    __syncthreads();
    if (sub < 32) {
        float a = catb[sub];
        #pragma unroll
        for (int k = 0; k < 24; k++) a += s_x[ln][k] * catW[k * 32 + sub];
        s_s[ln][sub] = fmaxf(a, 0.f);
    }
    __syncthreads();
    float a = initb[sub];
    #pragma unroll
    for (int k = 0; k < 16; k++) a += s_x[ln][24 + k] * initW[k * 64 + sub];
    #pragma unroll
    for (int k = 0; k < 32; k++) a += s_s[ln][k] * initW[(16 + k) * 64 + sub];
    g_h[n * 64 + sub] = fmaxf(a, 0.f);
}

// ---------------- linear 1: h[N,64] @ Wl/Wr[64,256] -> xl1,xr1 -------------
__global__ void k_lin1(const float* __restrict__ Wl, const float* __restrict__ bl,
                       const float* __restrict__ Wr, const float* __restrict__ br) {
    __shared__ float xs[8][64];
    int j = threadIdx.x;
    int base = blockIdx.x * 8;
    for (int t = j; t < 8 * 64; t += 256)
        xs[t >> 6][t & 63] = g_h[(base + (t >> 6)) * 64 + (t & 63)];
    __syncthreads();
    float al[8], ar[8];
    float bbl = bl[j], bbr = br[j];
    #pragma unroll
    for (int n = 0; n < 8; n++) { al[n] = bbl; ar[n] = bbr; }
    for (int k = 0; k < 64; k++) {
        float wl = Wl[k * 256 + j];
        float wr = Wr[k * 256 + j];
        #pragma unroll
        for (int n = 0; n < 8; n++) {
            float xv = xs[n][k];
            al[n] = fmaf(xv, wl, al[n]);
            ar[n] = fmaf(xv, wr, ar[n]);
        }
    }
    #pragma unroll
    for (int n = 0; n < 8; n++) {
        g_xl1[(base + n) * 256 + j] = al[n];
        g_xr1[(base + n) * 256 + j] = ar[n];
    }
}

// ---------------- GAT layer 1 (4 heads x 64): warp per dst node ------------
// float2 index idx = lane + 32*i covers channels (2*idx, 2*idx+1); head = i.
__global__ void k_gat1(const float* __restrict__ att, const float* __restrict__ bias) {
    int w = (blockIdx.x * blockDim.x + threadIdx.x) >> 5;
    int lane = threadIdx.x & 31;
    if (w >= NN) return;
    const float2* xrp  = (const float2*)(g_xr1 + (long)w * 256);
    const float2* attp = (const float2*)att;
    float2 xr[4], at[4], acc[4];
    float m[4], den[4];
    #pragma unroll
    for (int i = 0; i < 4; i++) {
        int idx = lane + 32 * i;
        xr[i]  = xrp[idx];
        at[i]  = attp[idx];
        acc[i] = make_float2(0.f, 0.f);
        m[i] = -1e30f; den[i] = 0.f;
    }
    int p0 = g_rowptr[w], p1 = g_rowptr[w + 1];
    for (int p = p0; p < p1; p++) {
        int s = g_csr[p];
        s = s < 0 ? 0 : (s >= NN ? NN - 1 : s);
        const float2* xlp = (const float2*)(g_xl1 + (long)s * 256);
        float2 xl[4];
        float part[4];
        #pragma unroll
        for (int i = 0; i < 4; i++) {
            xl[i] = __ldg(&xlp[lane + 32 * i]);
            float v0 = xl[i].x + xr[i].x;
            float v1 = xl[i].y + xr[i].y;
            float t0 = fmaxf(v0, 0.2f * v0);
            float t1 = fmaxf(v1, 0.2f * v1);
            part[i] = fmaf(t0, at[i].x, t1 * at[i].y);
        }
        #pragma unroll
        for (int off = 16; off > 0; off >>= 1) {
            #pragma unroll
            for (int h = 0; h < 4; h++)
                part[h] += __shfl_xor_sync(0xffffffffu, part[h], off);
        }
        #pragma unroll
        for (int h = 0; h < 4; h++) {
            float e  = part[h];
            float mn = fmaxf(m[h], e);
            float sc = __expf(m[h] - mn);
            float wv = __expf(e - mn);
            den[h] = den[h] * sc + wv;
            m[h] = mn;
            acc[h].x = acc[h].x * sc + wv * xl[h].x;
            acc[h].y = acc[h].y * sc + wv * xl[h].y;
        }
    }
    float2* outp = (float2*)(g_h1 + (long)w * 256);
    const float2* bp = (const float2*)bias;
    #pragma unroll
    for (int i = 0; i < 4; i++) {
        int idx = lane + 32 * i;
        float2 bv = bp[idx];
        float inv = 1.f / den[i];
        float v0 = acc[i].x * inv + bv.x;
        float v1 = acc[i].y * inv + bv.y;
        v0 = v0 > 0.f ? v0 : (__expf(v0) - 1.f);
        v1 = v1 > 0.f ? v1 : (__expf(v1) - 1.f);
        outp[idx] = make_float2(v0, v1);
    }
}

// ---------------- linear 2: h1[N,256] @ Wl/Wr[256,64] -> xl2,xr2 -----------
__global__ void k_lin2(const float* __restrict__ Wl, const float* __restrict__ bl,
                       const float* __restrict__ Wr, const float* __restrict__ br) {
    __shared__ float xs[16][256];
    int tid = threadIdx.x;
    int j = tid & 63;
    int q = tid >> 6;
    int base = blockIdx.x * 16;
    for (int t = tid; t < 16 * 256; t += 256)
        xs[t >> 8][t & 255] = g_h1[(long)(base + (t >> 8)) * 256 + (t & 255)];
    __syncthreads();
    float al[4], ar[4];
    float bbl = bl[j], bbr = br[j];
    #pragma unroll
    for (int n = 0; n < 4; n++) { al[n] = bbl; ar[n] = bbr; }
    for (int k = 0; k < 256; k++) {
        float wl = Wl[k * 64 + j];
        float wr = Wr[k * 64 + j];
        #pragma unroll
        for (int n = 0; n < 4; n++) {
            float xv = xs[q + 4 * n][k];
            al[n] = fmaf(xv, wl, al[n]);
            ar[n] = fmaf(xv, wr, ar[n]);
        }
    }
    #pragma unroll
    for (int n = 0; n < 4; n++) {
        int node = base + q + 4 * n;
        g_xl2[node * 64 + j] = al[n];
        g_xr2[node * 64 + j] = ar[n];
    }
}

// ---------------- GAT layer 2 (1 head x 64): warp per dst node -------------
__global__ void k_gat2(const float* __restrict__ att, const float* __restrict__ bias) {
    int w = (blockIdx.x * blockDim.x + threadIdx.x) >> 5;
    int lane = threadIdx.x & 31;
    if (w >= NN) return;
    float2 xr = ((const float2*)(g_xr2 + (long)w * 64))[lane];
    float2 at = ((const float2*)att)[lane];
    float2 acc = make_float2(0.f, 0.f);
    float m = -1e30f, den = 0.f;

    int p0 = g_rowptr[w], p1 = g_rowptr[w + 1];
    for (int p = p0; p < p1; p++) {
        int s = g_csr[p];
        s = s < 0 ? 0 : (s >= NN ? NN - 1 : s);
        float2 xl = __ldg(&((const float2*)(g_xl2 + (long)s * 64))[lane]);
        float v0 = xl.x + xr.x, v1 = xl.y + xr.y;
        float t0 = fmaxf(v0, 0.2f * v0);
        float t1 = fmaxf(v1, 0.2f * v1);
        float part = fmaf(t0, at.x, t1 * at.y);
        #pragma unroll
        for (int off = 16; off > 0; off >>= 1)
            part += __shfl_xor_sync(0xffffffffu, part, off);
        float mn = fmaxf(m, part);
        float sc = __expf(m - mn);
        float wv = __expf(part - mn);
        den = den * sc + wv;
        m = mn;
        acc.x = acc.x * sc + wv * xl.x;
        acc.y = acc.y * sc + wv * xl.y;
    }
    float2 bv = ((const float2*)bias)[lane];
    float inv = 1.f / den;
    float v0 = acc.x * inv + bv.x;
    float v1 = acc.y * inv + bv.y;
    v0 = v0 > 0.f ? v0 : (__expf(v0) - 1.f);
    v1 = v1 > 0.f ? v1 : (__expf(v1) - 1.f);
    ((float2*)(g_h2 + (long)w * 64))[lane] = make_float2(v0, v1);
}

// ---------------- mean pool (batch is sorted: register-run accumulation) ---
// block = 128 threads = 2 groups of 64 lanes; each group handles 32 nodes.
// Block b covers nodes [b*64, b*64+64). Every node covered exactly once.
__global__ void k_pool(const int* __restrict__ batch) {
    int tid = threadIdx.x;
    int grp = tid >> 6;
    int j   = tid & 63;
    int n0 = blockIdx.x * 64 + grp * 32;
    int is64 = g_is64;
    float acc = 0.f;
    int cnt = 0, prev = -1;
    for (int k = 0; k < 32; k++) {
        int n = n0 + k;
        if (n >= NN) break;
        int g = ld_idx(batch, n, is64, NG);
        if (g != prev) {
            if (prev >= 0) {
                atomicAdd(&g_sums[prev * 64 + j], acc);
                if (j == 0) atomicAdd(&g_cnts[prev], cnt);
            }
            acc = 0.f; cnt = 0; prev = g;
        }
        acc += g_h2[n * 64 + j];
        cnt++;
    }
    if (prev >= 0) {
        atomicAdd(&g_sums[prev * 64 + j], acc);
        if (j == 0) atomicAdd(&g_cnts[prev], cnt);
    }
}

// ---------------- output head ----------------------------------------------
__global__ void k_out(const float* __restrict__ W, const float* __restrict__ b,
                      float* __restrict__ out) {
    int t = blockIdx.x * blockDim.x + threadIdx.x;
    if (t >= NG * 64) return;
    int g = t >> 6, j = t & 63;
    float c = fmaxf((float)g_cnts[g], 1.f);
    float inv = 1.f / c;
    float a = b[j];
    #pragma unroll
    for (int k = 0; k < 64; k++)
        a = fmaf(g_sums[g * 64 + k] * inv, W[k * 64 + j], a);
    out[t] = a;
}

// ---------------- launch ----------------------------------------------------
extern "C" void kernel_launch(void* const* d_in, const int* in_sizes, int n_in,
                              void* d_out, int out_size) {
    static const int EXP[21] = {
        2000000, 1600000, 50000,
        768, 32, 3072, 64,
        16384, 256, 16384, 256,
        256, 256,
        16384, 64, 16384, 64,
        64, 64,
        4096, 64
    };
    const void* in[21];
    bool direct = (n_in >= 21);
    if (direct)
        for (int i = 0; i < 21; i++)
            if (in_sizes[i] != EXP[i]) { direct = false; break; }
    if (direct) {
        for (int i = 0; i < 21; i++) in[i] = d_in[i];
    } else {
        bool used[64] = {false};
        for (int j = 0; j < 21; j++) {
            in[j] = d_in[j < n_in ? j : 0];
            for (int i = 0; i < n_in && i < 64; i++) {
                if (!used[i] && in_sizes[i] == EXP[j]) {
                    in[j] = d_in[i]; used[i] = true; break;
                }
            }
        }
    }

    const float* x      = (const float*)in[0];
    const int*   ei     = (const int*)in[1];
    const int*   batch  = (const int*)in[2];
    const float* cat_W  = (const float*)in[3];
    const float* cat_b  = (const float*)in[4];
    const float* init_W = (const float*)in[5];
    const float* init_b = (const float*)in[6];
    const float* c1_Wl  = (const float*)in[7];
    const float* c1_bl  = (const float*)in[8];
    const float* c1_Wr  = (const float*)in[9];
    const float* c1_br  = (const float*)in[10];
    const float* c1_att = (const float*)in[11];
    const float* c1_bias= (const float*)in[12];
    const float* c2_Wl  = (const float*)in[13];
    const float* c2_bl  = (const float*)in[14];
    const float* c2_Wr  = (const float*)in[15];
    const float* c2_br  = (const float*)in[16];
    const float* c2_att = (const float*)in[17];
    const float* c2_bias= (const float*)in[18];
    const float* out_W  = (const float*)in[19];
    const float* out_b  = (const float*)in[20];
    float* out = (float*)d_out;

    k_init<<<(NN + 255) / 256, 256>>>(ei);
    k_deg<<<(NE + 255) / 256, 256>>>(ei);
    k_scan1<<<NB, 256>>>();
    k_scan2<<<1, 256>>>();
    k_scan3<<<NB, 256>>>();
    k_scatter<<<(ET + 255) / 256, 256>>>(ei);

    k_node<<<NN / 4, 256>>>(x, cat_W, cat_b, init_W, init_b);
    k_lin1<<<NN / 8, 256>>>(c1_Wl, c1_bl, c1_Wr, c1_br);
    k_gat1<<<NN / 8, 256>>>(c1_att, c1_bias);
    k_lin2<<<NN / 16, 256>>>(c2_Wl, c2_bl, c2_Wr, c2_br);
    k_gat2<<<NN / 8, 256>>>(c2_att, c2_bias);
    k_pool<<<(NN + 63) / 64, 128>>>(batch);
    k_out<<<16, 256>>>(out_W, out_b, out);
}

// round 6
// speedup vs baseline: 1.4804x; 1.1137x over previous
#include <cuda_runtime.h>
#include <cuda_fp16.h>

#define NN 50000
#define NE 800000
#define ET (NN + NE)      // edges + self loops
#define NG 64
#define NB 196            // scan blocks: ceil(NN/256)

// ---------------- scratch (static device globals; no runtime alloc) --------
__device__ float  g_h   [NN * 64];   // after init MLP
__device__ __half g_xl1h[NN * 256];  // gathered operand, fp16
__device__ float  g_xr1 [NN * 256];
__device__ float  g_h1  [NN * 256];  // GAT1 output (post-ELU)
__device__ __half g_xl2h[NN * 64];   // gathered operand, fp16
__device__ float  g_xr2 [NN * 64];
__device__ float  g_h2  [NN * 64];   // GAT2 output (post-ELU)
__device__ int    g_deg[NN];
__device__ int    g_rowptr[NN + 1];
__device__ int    g_cursor[NN];
__device__ int    g_csr[ET];         // src per incoming edge, grouped by dst
__device__ int    g_bsum[256];
__device__ int    g_boff[256];
__device__ float  g_sums[NG * 64];
__device__ int    g_cnts[NG];
__device__ int    g_is64;            // 1 if index tensors are int64, 0 if int32

// ---------------- index helpers --------------------------------------------
__device__ __forceinline__ int ld_idx(const int* __restrict__ p, int i, int is64, int lim) {
    int v = is64 ? p[2 * i] : p[i];
    v = v < 0 ? 0 : v;
    v = v >= lim ? lim - 1 : v;
    return v;
}

// ---------------- init + dtype detect --------------------------------------
__global__ void k_init(const int* __restrict__ ei32) {
    int t = blockIdx.x * blockDim.x + threadIdx.x;
    if (t < NN) g_deg[t] = 1;                 // self loop
    if (t < NG * 64) g_sums[t] = 0.f;
    if (t < NG) g_cnts[t] = 0;
    if (blockIdx.x == 0 && threadIdx.x < 32) {
        int lane = threadIdx.x;
        int nz = 0;
        #pragma unroll
        for (int i = 0; i < 8; i++) {
            nz |= ei32[2 * (lane * 8 + i) + 1];
            nz |= ei32[NE + 2 * (lane * 8 + i) + 1];
        }
        #pragma unroll
        for (int off = 16; off > 0; off >>= 1)
            nz |= __shfl_xor_sync(0xffffffffu, nz, off);
        if (lane == 0) g_is64 = (nz == 0) ? 1 : 0;
    }
}

__global__ void k_deg(const int* __restrict__ ei) {
    int e = blockIdx.x * blockDim.x + threadIdx.x;
    if (e < NE) {
        int d = ld_idx(ei, NE + e, g_is64, NN);
        atomicAdd(&g_deg[d], 1);
    }
}

// ---------------- parallel 3-phase scan ------------------------------------
__global__ void k_scan1() {
    __shared__ int sh[256];
    int t = threadIdx.x;
    int i = blockIdx.x * 256 + t;
    sh[t] = (i < NN) ? g_deg[i] : 0;
    __syncthreads();
    #pragma unroll
    for (int off = 128; off > 0; off >>= 1) {
        if (t < off) sh[t] += sh[t + off];
        __syncthreads();
    }
    if (t == 0) g_bsum[blockIdx.x] = sh[0];
}

__global__ void k_scan2() {
    __shared__ int sh[256];
    int t = threadIdx.x;
    int own = (t < NB) ? g_bsum[t] : 0;
    sh[t] = own;
    __syncthreads();
    #pragma unroll
    for (int off = 1; off < 256; off <<= 1) {
        int v = (t >= off) ? sh[t - off] : 0;
        __syncthreads();
        sh[t] += v;
        __syncthreads();
    }
    if (t < NB) g_boff[t] = sh[t] - own;      // exclusive
    if (t == 255) g_rowptr[NN] = sh[255];
}

__global__ void k_scan3() {
    __shared__ int sh[256];
    int t = threadIdx.x;
    int i = blockIdx.x * 256 + t;
    int d = (i < NN) ? g_deg[i] : 0;
    sh[t] = d;
    __syncthreads();
    #pragma unroll
    for (int off = 1; off < 256; off <<= 1) {
        int v = (t >= off) ? sh[t - off] : 0;
        __syncthreads();
        sh[t] += v;
        __syncthreads();
    }
    if (i < NN) {
        int excl = sh[t] - d + g_boff[blockIdx.x];
        g_rowptr[i] = excl;
        g_cursor[i] = excl;
    }
}

__global__ void k_scatter(const int* __restrict__ ei) {
    int e = blockIdx.x * blockDim.x + threadIdx.x;
    int is64 = g_is64;
    if (e < NE) {
        int s = ld_idx(ei, e, is64, NN);
        int d = ld_idx(ei, NE + e, is64, NN);
        int p = atomicAdd(&g_cursor[d], 1);
        if (p < ET) g_csr[p] = s;
    } else if (e < ET) {
        int i = e - NE;
        int p = atomicAdd(&g_cursor[i], 1);
        if (p < ET) g_csr[p] = i;              // self loop
    }
}

// ---------------- node feature MLP -----------------------------------------
__global__ void k_node(const float* __restrict__ x,
                       const float* __restrict__ catW, const float* __restrict__ catb,
                       const float* __restrict__ initW, const float* __restrict__ initb) {
    __shared__ float s_x[4][40];
    __shared__ float s_s[4][32];
    int sub = threadIdx.x & 63;
    int ln  = threadIdx.x >> 6;
    int n = blockIdx.x * 4 + ln;
    if (sub < 40) s_x[ln][sub] = x[n * 40 + sub];
    __syncthreads();
    if (sub < 32) {
        float a = catb[sub];
        #pragma unroll
        for (int k = 0; k < 24; k++) a += s_x[ln][k] * catW[k * 32 + sub];
        s_s[ln][sub] = fmaxf(a, 0.f);
    }
    __syncthreads();
    float a = initb[sub];
    #pragma unroll
    for (int k = 0; k < 16; k++) a += s_x[ln][24 + k] * initW[k * 64 + sub];
    #pragma unroll
    for (int k = 0; k < 32; k++) a += s_s[ln][k] * initW[(16 + k) * 64 + sub];
    g_h[n * 64 + sub] = fmaxf(a, 0.f);
}

// ---------------- linear 1: h[N,64] @ Wl/Wr[64,256] -> xl1h,xr1 ------------
__global__ void k_lin1(const float* __restrict__ Wl, const float* __restrict__ bl,
                       const float* __restrict__ Wr, const float* __restrict__ br) {
    __shared__ float xs[8][64];
    int j = threadIdx.x;
    int base = blockIdx.x * 8;
    for (int t = j; t < 8 * 64; t += 256)
        xs[t >> 6][t & 63] = g_h[(base + (t >> 6)) * 64 + (t & 63)];
    __syncthreads();
    float al[8], ar[8];
    float bbl = bl[j], bbr = br[j];
    #pragma unroll
    for (int n = 0; n < 8; n++) { al[n] = bbl; ar[n] = bbr; }
    for (int k = 0; k < 64; k++) {
        float wl = Wl[k * 256 + j];
        float wr = Wr[k * 256 + j];
        #pragma unroll
        for (int n = 0; n < 8; n++) {
            float xv = xs[n][k];
            al[n] = fmaf(xv, wl, al[n]);
            ar[n] = fmaf(xv, wr, ar[n]);
        }
    }
    #pragma unroll
    for (int n = 0; n < 8; n++) {
        g_xl1h[(base + n) * 256 + j] = __float2half(al[n]);
        g_xr1 [(base + n) * 256 + j] = ar[n];
    }
}

// ---------------- GAT layer 1 (4 heads x 64): warp per dst node ------------
// Lane owns 8 contiguous channels c0 = 8*lane .. 8*lane+7 (head = lane>>3).
// Per edge: ONE 16B load per lane, 3-shfl reduction within the 8-lane head
// group, scalar online-softmax state per lane.
__global__ void k_gat1(const float* __restrict__ att, const float* __restrict__ bias) {
    int w = (blockIdx.x * blockDim.x + threadIdx.x) >> 5;
    int lane = threadIdx.x & 31;
    if (w >= NN) return;
    const float2* xrp  = (const float2*)(g_xr1 + (long)w * 256);
    const float2* attp = (const float2*)att;
    float2 xr[4], at[4], acc[4];
    #pragma unroll
    for (int i = 0; i < 4; i++) {
        xr[i]  = xrp[4 * lane + i];       // channel pairs (8l+2i, 8l+2i+1)
        at[i]  = attp[4 * lane + i];
        acc[i] = make_float2(0.f, 0.f);
    }
    float m = -1e30f, den = 0.f;

    int p0 = g_rowptr[w], p1 = g_rowptr[w + 1];
    for (int p = p0; p < p1; p++) {
        int s = g_csr[p];
        s = s < 0 ? 0 : (s >= NN ? NN - 1 : s);
        // 8 halves = 16B per lane: halves [8*lane .. 8*lane+7] of row s
        float4 raw = __ldg((const float4*)(g_xl1h + (long)s * 256) + lane);
        __half2 h0 = *(__half2*)&raw.x;
        __half2 h1 = *(__half2*)&raw.y;
        __half2 h2 = *(__half2*)&raw.z;
        __half2 h3 = *(__half2*)&raw.w;
        float2 xl[4];
        xl[0] = __half22float2(h0);
        xl[1] = __half22float2(h1);
        xl[2] = __half22float2(h2);
        xl[3] = __half22float2(h3);
        float part = 0.f;
        #pragma unroll
        for (int i = 0; i < 4; i++) {
            float v0 = xl[i].x + xr[i].x;
            float v1 = xl[i].y + xr[i].y;
            float t0 = fmaxf(v0, 0.2f * v0);
            float t1 = fmaxf(v1, 0.2f * v1);
            part += t0 * at[i].x + t1 * at[i].y;
        }
        // reduce within 8-lane head group (lanes with same lane>>3)
        part += __shfl_xor_sync(0xffffffffu, part, 4);
        part += __shfl_xor_sync(0xffffffffu, part, 2);
        part += __shfl_xor_sync(0xffffffffu, part, 1);
        // scalar online softmax (per lane = per head, replicated in group)
        float mn = fmaxf(m, part);
        float sc = __expf(m - mn);
        float wv = __expf(part - mn);
        den = den * sc + wv;
        m = mn;
        #pragma unroll
        for (int i = 0; i < 4; i++) {
            acc[i].x = acc[i].x * sc + wv * xl[i].x;
            acc[i].y = acc[i].y * sc + wv * xl[i].y;
        }
    }
    const float2* bp = (const float2*)bias;
    float inv = 1.f / den;
    float o[8];
    #pragma unroll
    for (int i = 0; i < 4; i++) {
        float2 bv = bp[4 * lane + i];
        float v0 = acc[i].x * inv + bv.x;
        float v1 = acc[i].y * inv + bv.y;
        o[2 * i]     = v0 > 0.f ? v0 : (__expf(v0) - 1.f);
        o[2 * i + 1] = v1 > 0.f ? v1 : (__expf(v1) - 1.f);
    }
    float4* outp = (float4*)(g_h1 + (long)w * 256 + 8 * lane);
    outp[0] = make_float4(o[0], o[1], o[2], o[3]);
    outp[1] = make_float4(o[4], o[5], o[6], o[7]);
}

// ---------------- linear 2: h1[N,256] @ Wl/Wr[256,64] -> xl2h,xr2 ----------
__global__ void k_lin2(const float* __restrict__ Wl, const float* __restrict__ bl,
                       const float* __restrict__ Wr, const float* __restrict__ br) {
    __shared__ float xs[16][256];
    int tid = threadIdx.x;
    int j = tid & 63;
    int q = tid >> 6;
    int base = blockIdx.x * 16;
    for (int t = tid; t < 16 * 256; t += 256)
        xs[t >> 8][t & 255] = g_h1[(long)(base + (t >> 8)) * 256 + (t & 255)];
    __syncthreads();
    float al[4], ar[4];
    float bbl = bl[j], bbr = br[j];
    #pragma unroll
    for (int n = 0; n < 4; n++) { al[n] = bbl; ar[n] = bbr; }
    for (int k = 0; k < 256; k++) {
        float wl = Wl[k * 64 + j];
        float wr = Wr[k * 64 + j];
        #pragma unroll
        for (int n = 0; n < 4; n++) {
            float xv = xs[q + 4 * n][k];
            al[n] = fmaf(xv, wl, al[n]);
            ar[n] = fmaf(xv, wr, ar[n]);
        }
    }
    #pragma unroll
    for (int n = 0; n < 4; n++) {
        int node = base + q + 4 * n;
        g_xl2h[node * 64 + j] = __float2half(al[n]);
        g_xr2 [node * 64 + j] = ar[n];
    }
}

// ---------------- GAT layer 2 (1 head x 64): warp per dst node -------------
// lane covers channel pair (2*lane, 2*lane+1)
__global__ void k_gat2(const float* __restrict__ att, const float* __restrict__ bias) {
    int w = (blockIdx.x * blockDim.x + threadIdx.x) >> 5;
    int lane = threadIdx.x & 31;
    if (w >= NN) return;
    float2 xr = ((const float2*)(g_xr2 + (long)w * 64))[lane];
    float2 at = ((const float2*)att)[lane];
    float2 acc = make_float2(0.f, 0.f);
    float m = -1e30f, den = 0.f;

    int p0 = g_rowptr[w], p1 = g_rowptr[w + 1];
    for (int p = p0; p < p1; p++) {
        int s = g_csr[p];
        s = s < 0 ? 0 : (s >= NN ? NN - 1 : s);
        __half2 hx = __ldg((const __half2*)(g_xl2h + (long)s * 64) + lane);
        float2 xl = __half22float2(hx);
        float v0 = xl.x + xr.x, v1 = xl.y + xr.y;
        float t0 = fmaxf(v0, 0.2f * v0);
        float t1 = fmaxf(v1, 0.2f * v1);
        float part = fmaf(t0, at.x, t1 * at.y);
        #pragma unroll
        for (int off = 16; off > 0; off >>= 1)
            part += __shfl_xor_sync(0xffffffffu, part, off);
        float mn = fmaxf(m, part);
        float sc = __expf(m - mn);
        float wv = __expf(part - mn);
        den = den * sc + wv;
        m = mn;
        acc.x = acc.x * sc + wv * xl.x;
        acc.y = acc.y * sc + wv * xl.y;
    }
    float2 bv = ((const float2*)bias)[lane];
    float inv = 1.f / den;
    float v0 = acc.x * inv + bv.x;
    float v1 = acc.y * inv + bv.y;
    v0 = v0 > 0.f ? v0 : (__expf(v0) - 1.f);
    v1 = v1 > 0.f ? v1 : (__expf(v1) - 1.f);
    ((float2*)(g_h2 + (long)w * 64))[lane] = make_float2(v0, v1);
}

// ---------------- mean pool (batch is sorted: register-run accumulation) ---
// Block b covers nodes [b*64, b*64+64); 2 groups of 64 lanes, 32 nodes each.
__global__ void k_pool(const int* __restrict__ batch) {
    int tid = threadIdx.x;
    int grp = tid >> 6;
    int j   = tid & 63;
    int n0 = blockIdx.x * 64 + grp * 32;
    int is64 = g_is64;
    float acc = 0.f;
    int cnt = 0, prev = -1;
    for (int k = 0; k < 32; k++) {
        int n = n0 + k;
        if (n >= NN) break;
        int g = ld_idx(batch, n, is64, NG);
        if (g != prev) {
            if (prev >= 0) {
                atomicAdd(&g_sums[prev * 64 + j], acc);
                if (j == 0) atomicAdd(&g_cnts[prev], cnt);
            }
            acc = 0.f; cnt = 0; prev = g;
        }
        acc += g_h2[n * 64 + j];
        cnt++;
    }
    if (prev >= 0) {
        atomicAdd(&g_sums[prev * 64 + j], acc);
        if (j == 0) atomicAdd(&g_cnts[prev], cnt);
    }
}

// ---------------- output head ----------------------------------------------
__global__ void k_out(const float* __restrict__ W, const float* __restrict__ b,
                      float* __restrict__ out) {
    int t = blockIdx.x * blockDim.x + threadIdx.x;
    if (t >= NG * 64) return;
    int g = t >> 6, j = t & 63;
    float c = fmaxf((float)g_cnts[g], 1.f);
    float inv = 1.f / c;
    float a = b[j];
    #pragma unroll
    for (int k = 0; k < 64; k++)
        a = fmaf(g_sums[g * 64 + k] * inv, W[k * 64 + j], a);
    out[t] = a;
}

// ---------------- launch ----------------------------------------------------
extern "C" void kernel_launch(void* const* d_in, const int* in_sizes, int n_in,
                              void* d_out, int out_size) {
    static const int EXP[21] = {
        2000000, 1600000, 50000,
        768, 32, 3072, 64,
        16384, 256, 16384, 256,
        256, 256,
        16384, 64, 16384, 64,
        64, 64,
        4096, 64
    };
    const void* in[21];
    bool direct = (n_in >= 21);
    if (direct)
        for (int i = 0; i < 21; i++)
            if (in_sizes[i] != EXP[i]) { direct = false; break; }
    if (direct) {
        for (int i = 0; i < 21; i++) in[i] = d_in[i];
    } else {
        bool used[64] = {false};
        for (int j = 0; j < 21; j++) {
            in[j] = d_in[j < n_in ? j : 0];
            for (int i = 0; i < n_in && i < 64; i++) {
                if (!used[i] && in_sizes[i] == EXP[j]) {
                    in[j] = d_in[i]; used[i] = true; break;
                }
            }
        }
    }

    const float* x      = (const float*)in[0];
    const int*   ei     = (const int*)in[1];
    const int*   batch  = (const int*)in[2];
    const float* cat_W  = (const float*)in[3];
    const float* cat_b  = (const float*)in[4];
    const float* init_W = (const float*)in[5];
    const float* init_b = (const float*)in[6];
    const float* c1_Wl  = (const float*)in[7];
    const float* c1_bl  = (const float*)in[8];
    const float* c1_Wr  = (const float*)in[9];
    const float* c1_br  = (const float*)in[10];
    const float* c1_att = (const float*)in[11];
    const float* c1_bias= (const float*)in[12];
    const float* c2_Wl  = (const float*)in[13];
    const float* c2_bl  = (const float*)in[14];
    const float* c2_Wr  = (const float*)in[15];
    const float* c2_br  = (const float*)in[16];
    const float* c2_att = (const float*)in[17];
    const float* c2_bias= (const float*)in[18];
    const float* out_W  = (const float*)in[19];
    const float* out_b  = (const float*)in[20];
    float* out = (float*)d_out;

    k_init<<<(NN + 255) / 256, 256>>>(ei);
    k_deg<<<(NE + 255) / 256, 256>>>(ei);
    k_scan1<<<NB, 256>>>();
    k_scan2<<<1, 256>>>();
    k_scan3<<<NB, 256>>>();
    k_scatter<<<(ET + 255) / 256, 256>>>(ei);

    k_node<<<NN / 4, 256>>>(x, cat_W, cat_b, init_W, init_b);
    k_lin1<<<NN / 8, 256>>>(c1_Wl, c1_bl, c1_Wr, c1_br);
    k_gat1<<<NN / 8, 256>>>(c1_att, c1_bias);
    k_lin2<<<NN / 16, 256>>>(c2_Wl, c2_bl, c2_Wr, c2_br);
    k_gat2<<<NN / 8, 256>>>(c2_att, c2_bias);
    k_pool<<<(NN + 63) / 64, 128>>>(batch);
    k_out<<<16, 256>>>(out_W, out_b, out);
}

// round 8
// speedup vs baseline: 1.6845x; 1.1379x over previous
#include <cuda_runtime.h>
#include <cuda_fp16.h>

#define NN 50000
#define NE 800000
#define ET (NN + NE)      // edges + self loops
#define NG 64
#define NB 196            // scan blocks: ceil(NN/256)

// ---------------- scratch (static device globals; zero-initialized) --------
// Invariant: g_deg, g_sums, g_cnts are all-zero at kernel_launch entry;
// each launch restores them to zero after use (k_scan23 / k_out).
__device__ __half g_xl1h[NN * 256];  // gathered operand, fp16
__device__ float  g_xr1 [NN * 256];
__device__ float  g_h1  [NN * 256];  // GAT1 output (post-ELU)
__device__ __half g_xl2h[NN * 64];   // gathered operand, fp16
__device__ float  g_xr2 [NN * 64];
__device__ float  g_h2  [NN * 64];   // GAT2 output (post-ELU)
__device__ int    g_deg[NN];         // real in-edge count (self loop implicit)
__device__ int    g_rowptr[NN + 1];
__device__ int    g_cursor[NN];
__device__ int    g_csr[ET];         // src per incoming edge, grouped by dst
__device__ int    g_bsum[256];
__device__ float  g_sums[NG * 64];
__device__ int    g_cnts[NG];
__device__ int    g_is64;            // 1 if index tensors are int64

// ---------------- index helpers --------------------------------------------
__device__ __forceinline__ int ld_idx(const int* __restrict__ p, int i, int is64, int lim) {
    int v = is64 ? p[2 * i] : p[i];
    v = v < 0 ? 0 : v;
    v = v >= lim ? lim - 1 : v;
    return v;
}

// ---------------- fused node MLP + linear1 ---------------------------------
// block = 256 threads handles 8 nodes.
__global__ void k_nodelin1(const float* __restrict__ x,
                           const float* __restrict__ catW, const float* __restrict__ catb,
                           const float* __restrict__ initW, const float* __restrict__ initb,
                           const float* __restrict__ Wl, const float* __restrict__ bl,
                           const float* __restrict__ Wr, const float* __restrict__ br) {
    __shared__ float s_x[8][40];
    __shared__ float s_s[8][32];
    __shared__ float s_h[8][64];
    int tid = threadIdx.x;
    int base = blockIdx.x * 8;
    for (int t = tid; t < 8 * 40; t += 256) {
        int n = t / 40, c = t % 40;
        s_x[n][c] = x[(base + n) * 40 + c];
    }
    __syncthreads();
    {   // cat embedding: 8 nodes x 32 ch = 256, one per thread
        int n = tid >> 5, c = tid & 31;
        float a = catb[c];
        #pragma unroll
        for (int k = 0; k < 24; k++) a += s_x[n][k] * catW[k * 32 + c];
        s_s[n][c] = fmaxf(a, 0.f);
    }
    __syncthreads();
    #pragma unroll
    for (int r = 0; r < 2; r++) {   // init linear: 512 outputs, 2 per thread
        int t = tid + r * 256;
        int n = t >> 6, c = t & 63;
        float a = initb[c];
        #pragma unroll
        for (int k = 0; k < 16; k++) a += s_x[n][24 + k] * initW[k * 64 + c];
        #pragma unroll
        for (int k = 0; k < 32; k++) a += s_s[n][k] * initW[(16 + k) * 64 + c];
        s_h[n][c] = fmaxf(a, 0.f);
    }
    __syncthreads();
    // lin1: j = output col (0..255), 8 nodes per block
    int j = tid;
    float al[8], ar[8];
    float bbl = bl[j], bbr = br[j];
    #pragma unroll
    for (int n = 0; n < 8; n++) { al[n] = bbl; ar[n] = bbr; }
    for (int k = 0; k < 64; k++) {
        float wl = Wl[k * 256 + j];
        float wr = Wr[k * 256 + j];
        #pragma unroll
        for (int n = 0; n < 8; n++) {
            float xv = s_h[n][k];
            al[n] = fmaf(xv, wl, al[n]);
            ar[n] = fmaf(xv, wr, ar[n]);
        }
    }
    #pragma unroll
    for (int n = 0; n < 8; n++) {
        g_xl1h[(base + n) * 256 + j] = __float2half(al[n]);
        g_xr1 [(base + n) * 256 + j] = ar[n];
    }
}

// ---------------- degree count + per-warp dtype detect ----------------------
__global__ void k_deg(const int* __restrict__ ei) {
    // per-warp detect: under int64, odd 32-bit words of the first ids are the
    // (always-zero) hi words; under int32 they are random ids (nonzero w.h.p.)
    int lane = threadIdx.x & 31;
    int hw = ei[2 * lane + 1];
    int any32 = __any_sync(0xffffffffu, hw != 0);
    int is64 = !any32;
    int e = blockIdx.x * blockDim.x + threadIdx.x;
    if (e == 0) g_is64 = is64;
    if (e < NE) {
        int d = is64 ? ei[2 * (NE + e)] : ei[NE + e];
        d = d < 0 ? 0 : (d >= NN ? NN - 1 : d);
        atomicAdd(&g_deg[d], 1);
    }
}

// ---------------- scan phase 1: per-block sums ------------------------------
__global__ void k_scan1() {
    __shared__ int sh[256];
    int t = threadIdx.x;
    int i = blockIdx.x * 256 + t;
    sh[t] = (i < NN) ? g_deg[i] + 1 : 0;     // +1: implicit self loop
    __syncthreads();
    #pragma unroll
    for (int off = 128; off > 0; off >>= 1) {
        if (t < off) sh[t] += sh[t + off];
        __syncthreads();
    }
    if (t == 0) g_bsum[blockIdx.x] = sh[0];
}

// ---------------- scan phase 2+3 fused: rowptr + cursor; re-zero deg --------
__global__ void k_scan23() {
    __shared__ int pre[256];
    __shared__ int sh[256];
    int t = threadIdx.x;
    // every block redundantly scans the NB partials (cheap)
    pre[t] = (t < NB) ? g_bsum[t] : 0;
    __syncthreads();
    #pragma unroll
    for (int off = 1; off < 256; off <<= 1) {
        int v = (t >= off) ? pre[t - off] : 0;
        __syncthreads();
        pre[t] += v;
        __syncthreads();
    }
    int blockoff = (blockIdx.x == 0) ? 0 : pre[blockIdx.x - 1];
    int i = blockIdx.x * 256 + t;
    int d = (i < NN) ? g_deg[i] + 1 : 0;
    if (i < NN) g_deg[i] = 0;                 // restore zero-invariant
    sh[t] = d;
    __syncthreads();
    #pragma unroll
    for (int off = 1; off < 256; off <<= 1) {
        int v = (t >= off) ? sh[t - off] : 0;
        __syncthreads();
        sh[t] += v;
        __syncthreads();
    }
    if (i < NN) {
        int excl = sh[t] - d + blockoff;
        g_rowptr[i] = excl;
        g_cursor[i] = excl;
    }
    if (blockIdx.x == 0 && t == 0) g_rowptr[NN] = ET;
}

__global__ void k_scatter(const int* __restrict__ ei) {
    int e = blockIdx.x * blockDim.x + threadIdx.x;
    int is64 = g_is64;
    if (e < NE) {
        int s = ld_idx(ei, e, is64, NN);
        int d = ld_idx(ei, NE + e, is64, NN);
        int p = atomicAdd(&g_cursor[d], 1);
        if (p < ET) g_csr[p] = s;
    } else if (e < ET) {
        int i = e - NE;
        int p = atomicAdd(&g_cursor[i], 1);
        if (p < ET) g_csr[p] = i;              // self loop
    }
}

// ---------------- GAT layer 1 (4 heads x 64): warp per dst node ------------
// Lane owns 8 contiguous channels (head = lane>>3): one 16B fp16 load/edge,
// 3-shfl logit reduction, scalar softmax state. Next edge's row is
// prefetched before the shuffle/exp chain of the current edge.
__global__ void k_gat1(const float* __restrict__ att, const float* __restrict__ bias) {
    int w = (blockIdx.x * blockDim.x + threadIdx.x) >> 5;
    int lane = threadIdx.x & 31;
    if (w >= NN) return;
    const float2* xrp  = (const float2*)(g_xr1 + (long)w * 256);
    const float2* attp = (const float2*)att;
    float2 xr[4], at[4], acc[4];
    #pragma unroll
    for (int i = 0; i < 4; i++) {
        xr[i]  = xrp[4 * lane + i];
        at[i]  = attp[4 * lane + i];
        acc[i] = make_float2(0.f, 0.f);
    }
    float m = -1e30f, den = 0.f;

    int p0 = g_rowptr[w], p1 = g_rowptr[w + 1];
    int s0 = g_csr[p0];                              // deg >= 1 always
    float4 raw = __ldg((const float4*)(g_xl1h + (long)s0 * 256) + lane);
    for (int p = p0; p < p1; p++) {
        float4 cur = raw;
        if (p + 1 < p1) {                            // prefetch next edge row
            int sn = g_csr[p + 1];
            raw = __ldg((const float4*)(g_xl1h + (long)sn * 256) + lane);
        }
        float2 xl[4];
        xl[0] = __half22float2(*(__half2*)&cur.x);
        xl[1] = __half22float2(*(__half2*)&cur.y);
        xl[2] = __half22float2(*(__half2*)&cur.z);
        xl[3] = __half22float2(*(__half2*)&cur.w);
        float part = 0.f;
        #pragma unroll
        for (int i = 0; i < 4; i++) {
            float v0 = xl[i].x + xr[i].x;
            float v1 = xl[i].y + xr[i].y;
            float t0 = fmaxf(v0, 0.2f * v0);
            float t1 = fmaxf(v1, 0.2f * v1);
            part += t0 * at[i].x + t1 * at[i].y;
        }
        part += __shfl_xor_sync(0xffffffffu, part, 4);
        part += __shfl_xor_sync(0xffffffffu, part, 2);
        part += __shfl_xor_sync(0xffffffffu, part, 1);
        float mn = fmaxf(m, part);
        float sc = __expf(m - mn);
        float wv = __expf(part - mn);
        den = den * sc + wv;
        m = mn;
        #pragma unroll
        for (int i = 0; i < 4; i++) {
            acc[i].x = acc[i].x * sc + wv * xl[i].x;
            acc[i].y = acc[i].y * sc + wv * xl[i].y;
        }
    }
    const float2* bp = (const float2*)bias;
    float inv = 1.f / den;
    float o[8];
    #pragma unroll
    for (int i = 0; i < 4; i++) {
        float2 bv = bp[4 * lane + i];
        float v0 = acc[i].x * inv + bv.x;
        float v1 = acc[i].y * inv + bv.y;
        o[2 * i]     = v0 > 0.f ? v0 : (__expf(v0) - 1.f);
        o[2 * i + 1] = v1 > 0.f ? v1 : (__expf(v1) - 1.f);
    }
    float4* outp = (float4*)(g_h1 + (long)w * 256 + 8 * lane);
    outp[0] = make_float4(o[0], o[1], o[2], o[3]);
    outp[1] = make_float4(o[4], o[5], o[6], o[7]);
}

// ---------------- linear 2: h1[N,256] @ Wl/Wr[256,64] -> xl2h,xr2 ----------
__global__ void k_lin2(const float* __restrict__ Wl, const float* __restrict__ bl,
                       const float* __restrict__ Wr, const float* __restrict__ br) {
    __shared__ float xs[16][256];
    int tid = threadIdx.x;
    int j = tid & 63;
    int q = tid >> 6;
    int base = blockIdx.x * 16;
    for (int t = tid; t < 16 * 256; t += 256)
        xs[t >> 8][t & 255] = g_h1[(long)(base + (t >> 8)) * 256 + (t & 255)];
    __syncthreads();
    float al[4], ar[4];
    float bbl = bl[j], bbr = br[j];
    #pragma unroll
    for (int n = 0; n < 4; n++) { al[n] = bbl; ar[n] = bbr; }
    for (int k = 0; k < 256; k++) {
        float wl = __ldg(&Wl[k * 64 + j]);
        float wr = __ldg(&Wr[k * 64 + j]);
        #pragma unroll
        for (int n = 0; n < 4; n++) {
            float xv = xs[q + 4 * n][k];
            al[n] = fmaf(xv, wl, al[n]);
            ar[n] = fmaf(xv, wr, ar[n]);
        }
    }
    #pragma unroll
    for (int n = 0; n < 4; n++) {
        int node = base + q + 4 * n;
        g_xl2h[node * 64 + j] = __float2half(al[n]);
        g_xr2 [node * 64 + j] = ar[n];
    }
}

// ---------------- GAT layer 2 (1 head x 64): warp per dst node -------------
__global__ void k_gat2(const float* __restrict__ att, const float* __restrict__ bias) {
    int w = (blockIdx.x * blockDim.x + threadIdx.x) >> 5;
    int lane = threadIdx.x & 31;
    if (w >= NN) return;
    float2 xr = ((const float2*)(g_xr2 + (long)w * 64))[lane];
    float2 at = ((const float2*)att)[lane];
    float2 acc = make_float2(0.f, 0.f);
    float m = -1e30f, den = 0.f;

    int p0 = g_rowptr[w], p1 = g_rowptr[w + 1];
    int s0 = g_csr[p0];
    __half2 hraw = __ldg((const __half2*)(g_xl2h + (long)s0 * 64) + lane);
    for (int p = p0; p < p1; p++) {
        __half2 hcur = hraw;
        if (p + 1 < p1) {
            int sn = g_csr[p + 1];
            hraw = __ldg((const __half2*)(g_xl2h + (long)sn * 64) + lane);
        }
        float2 xl = __half22float2(hcur);
        float v0 = xl.x + xr.x, v1 = xl.y + xr.y;
        float t0 = fmaxf(v0, 0.2f * v0);
        float t1 = fmaxf(v1, 0.2f * v1);
        float part = fmaf(t0, at.x, t1 * at.y);
        #pragma unroll
        for (int off = 16; off > 0; off >>= 1)
            part += __shfl_xor_sync(0xffffffffu, part, off);
        float mn = fmaxf(m, part);
        float sc = __expf(m - mn);
        float wv = __expf(part - mn);
        den = den * sc + wv;
        m = mn;
        acc.x = acc.x * sc + wv * xl.x;
        acc.y = acc.y * sc + wv * xl.y;
    }
    float2 bv = ((const float2*)bias)[lane];
    float inv = 1.f / den;
    float v0 = acc.x * inv + bv.x;
    float v1 = acc.y * inv + bv.y;
    v0 = v0 > 0.f ? v0 : (__expf(v0) - 1.f);
    v1 = v1 > 0.f ? v1 : (__expf(v1) - 1.f);
    ((float2*)(g_h2 + (long)w * 64))[lane] = make_float2(v0, v1);
}

// ---------------- mean pool (batch is sorted: register-run accumulation) ---
__global__ void k_pool(const int* __restrict__ batch) {
    int tid = threadIdx.x;
    int grp = tid >> 6;
    int j   = tid & 63;
    int n0 = blockIdx.x * 64 + grp * 32;
    int is64 = g_is64;
    float acc = 0.f;
    int cnt = 0, prev = -1;
    for (int k = 0; k < 32; k++) {
        int n = n0 + k;
        if (n >= NN) break;
        int g = ld_idx(batch, n, is64, NG);
        if (g != prev) {
            if (prev >= 0) {
                atomicAdd(&g_sums[prev * 64 + j], acc);
                if (j == 0) atomicAdd(&g_cnts[prev], cnt);
            }
            acc = 0.f; cnt = 0; prev = g;
        }
        acc += g_h2[n * 64 + j];
        cnt++;
    }
    if (prev >= 0) {
        atomicAdd(&g_sums[prev * 64 + j], acc);
        if (j == 0) atomicAdd(&g_cnts[prev], cnt);
    }
}

// ---------------- output head (restores sums/cnts zero-invariant) ----------
__global__ void k_out(const float* __restrict__ W, const float* __restrict__ b,
                      float* __restrict__ out) {
    int t = blockIdx.x * blockDim.x + threadIdx.x;   // grid 16 x 256 = 4096
    int g = t >> 6, j = t & 63;
    float c = fmaxf((float)g_cnts[g], 1.f);
    float inv = 1.f / c;
    float a = b[j];
    #pragma unroll
    for (int k = 0; k < 64; k++)
        a = fmaf(g_sums[g * 64 + k] * inv, W[k * 64 + j], a);
    out[t] = a;
    __syncthreads();          // all reads of this block's sums/cnts done
    g_sums[t] = 0.f;
    if (j == 0) g_cnts[g] = 0;
}

// ---------------- launch ----------------------------------------------------
extern "C" void kernel_launch(void* const* d_in, const int* in_sizes, int n_in,
                              void* d_out, int out_size) {
    static const int EXP[21] = {
        2000000, 1600000, 50000,
        768, 32, 3072, 64,
        16384, 256, 16384, 256,
        256, 256,
        16384, 64, 16384, 64,
        64, 64,
        4096, 64
    };
    const void* in[21];
    bool direct = (n_in >= 21);
    if (direct)
        for (int i = 0; i < 21; i++)
            if (in_sizes[i] != EXP[i]) { direct = false; break; }
    if (direct) {
        for (int i = 0; i < 21; i++) in[i] = d_in[i];
    } else {
        bool used[64] = {false};
        for (int j = 0; j < 21; j++) {
            in[j] = d_in[j < n_in ? j : 0];
            for (int i = 0; i < n_in && i < 64; i++) {
                if (!used[i] && in_sizes[i] == EXP[j]) {
                    in[j] = d_in[i]; used[i] = true; break;
                }
            }
        }
    }

    const float* x      = (const float*)in[0];
    const int*   ei     = (const int*)in[1];
    const int*   batch  = (const int*)in[2];
    const float* cat_W  = (const float*)in[3];
    const float* cat_b  = (const float*)in[4];
    const float* init_W = (const float*)in[5];
    const float* init_b = (const float*)in[6];
    const float* c1_Wl  = (const float*)in[7];
    const float* c1_bl  = (const float*)in[8];
    const float* c1_Wr  = (const float*)in[9];
    const float* c1_br  = (const float*)in[10];
    const float* c1_att = (const float*)in[11];
    const float* c1_bias= (const float*)in[12];
    const float* c2_Wl  = (const float*)in[13];
    const float* c2_bl  = (const float*)in[14];
    const float* c2_Wr  = (const float*)in[15];
    const float* c2_br  = (const float*)in[16];
    const float* c2_att = (const float*)in[17];
    const float* c2_bias= (const float*)in[18];
    const float* out_W  = (const float*)in[19];
    const float* out_b  = (const float*)in[20];
    float* out = (float*)d_out;

    k_nodelin1<<<NN / 8, 256>>>(x, cat_W, cat_b, init_W, init_b,
                                c1_Wl, c1_bl, c1_Wr, c1_br);   // launch 0
    k_deg<<<(NE + 255) / 256, 256>>>(ei);                      // launch 1
    k_scan1<<<NB, 256>>>();                                    // launch 2
    k_scan23<<<NB, 256>>>();                                   // launch 3
    k_scatter<<<(ET + 255) / 256, 256>>>(ei);                  // launch 4
    k_gat1<<<NN / 8, 256>>>(c1_att, c1_bias);                  // launch 5 <- ncu
    k_lin2<<<NN / 16, 256>>>(c2_Wl, c2_bl, c2_Wr, c2_br);      // launch 6
    k_gat2<<<NN / 8, 256>>>(c2_att, c2_bias);                  // launch 7
    k_pool<<<(NN + 63) / 64, 128>>>(batch);                    // launch 8
    k_out<<<16, 256>>>(out_W, out_b, out);                     // launch 9
}